// round 13
// baseline (speedup 1.0000x reference)
#include <cuda_runtime.h>
#include <math.h>

#define DIM 2048
#define HID 8192
#define MAX_LEN 8192
#define NSPLIT 16
#define NSB ((MAX_LEN + 16) / 16)  // 513 score blocks (16 rows each)

// ---------------- scratch ----------------
__device__ float g_qkv[3 * DIM];            // q | k | v
__device__ float g_probs[MAX_LEN + 1];      // unnormalized exp(score)
__device__ float g_psum[NSB];               // per-block partial sums of exp
__device__ float g_invZ;                    // 1/sum(exp)
__device__ unsigned g_cnt;                  // last-block counter (self-resetting)
__device__ float g_partial[NSPLIT * DIM];   // split-K attention partials
__device__ float g_x2[DIM];                 // x + attn@oW + ob
__device__ float g_h[HID];                  // gelu(fc1)

__device__ __forceinline__ float warp_red(float v) {
#pragma unroll
    for (int o = 16; o > 0; o >>= 1) v += __shfl_xor_sync(0xffffffffu, v, o);
    return v;
}

// ---------------- kernel 1: fused rmsnorm + QKV GEMV (512 thr, 16 rows/blk, 384 blocks) ----------------
__global__ void __launch_bounds__(512)
k_qkv(const float* __restrict__ x, const float* __restrict__ anw,
      const float* __restrict__ qw, const float* __restrict__ qb,
      const float* __restrict__ kw, const float* __restrict__ kb,
      const float* __restrict__ vw, const float* __restrict__ vb) {
    __shared__ float s_xn[DIM];
    __shared__ float s_red[16];
    __shared__ float s_inv;
    int tid = threadIdx.x, warp = tid >> 5, lane = tid & 31;

    float4 v0 = reinterpret_cast<const float4*>(x)[tid];
    float ss = v0.x*v0.x + v0.y*v0.y + v0.z*v0.z + v0.w*v0.w;
    ss = warp_red(ss);
    if (lane == 0) s_red[warp] = ss;
    __syncthreads();
    if (tid == 0) {
        float t = 0.f;
#pragma unroll
        for (int i = 0; i < 16; i++) t += s_red[i];
        s_inv = rsqrtf(t * (1.f / DIM) + 1e-6f);
    }
    __syncthreads();
    float inv = s_inv;
    float4 n0 = reinterpret_cast<const float4*>(anw)[tid];
    float4* sx4 = reinterpret_cast<float4*>(s_xn);
    sx4[tid] = make_float4(v0.x*inv*n0.x, v0.y*inv*n0.y, v0.z*inv*n0.z, v0.w*inv*n0.w);
    __syncthreads();

    int r = blockIdx.x * 16 + warp;         // 0..6143
    int m = r >> 11, j = r & (DIM - 1);
    const float* W = (m == 0) ? qw : (m == 1) ? kw : vw;
    const float* B = (m == 0) ? qb : (m == 1) ? kb : vb;
    const float4* w4 = reinterpret_cast<const float4*>(W + (size_t)j * DIM);
    float acc = 0.f;
#pragma unroll 16
    for (int i = lane; i < DIM / 4; i += 32) {
        float4 a = __ldcs(&w4[i]); float4 b = sx4[i];
        acc += a.x*b.x + a.y*b.y + a.z*b.z + a.w*b.w;
    }
    acc = warp_red(acc);
    if (lane == 0) g_qkv[r] = acc + B[j];
}

// ---------------- kernel 2: scores -> exp, last block computes 1/Z (512 thr, 16 rows/blk) ----------------
__global__ void __launch_bounds__(512)
k_scores(const float* __restrict__ cacheK, const int* __restrict__ posp) {
    __shared__ float s_q[DIM];
    __shared__ float s_e[16];
    __shared__ float s_z[512];
    __shared__ bool s_last;
    int pos = *posp;
    int tid = threadIdx.x, warp = tid >> 5, lane = tid & 31;
    float4* sq4 = reinterpret_cast<float4*>(s_q);
    sq4[tid] = reinterpret_cast<const float4*>(g_qkv)[tid];
    if (tid < 16) s_e[tid] = 0.f;
    __syncthreads();

    int row = blockIdx.x * 16 + warp;
    if (row <= pos) {
        const float* krow = (row == pos) ? (g_qkv + DIM)
                                         : (cacheK + (size_t)row * DIM);
        const float4* k4 = reinterpret_cast<const float4*>(krow);
        float acc = 0.f;
#pragma unroll 16
        for (int i = lane; i < DIM / 4; i += 32) {
            float4 a = __ldcs(&k4[i]); float4 b = sq4[i];
            acc += a.x*b.x + a.y*b.y + a.z*b.z + a.w*b.w;
        }
        acc = warp_red(acc);
        if (lane == 0) {
            float e = __expf(acc * 0.022097086912079608f);  // 1/sqrt(2048)
            g_probs[row] = e;
            s_e[warp] = e;
        }
    }
    __syncthreads();
    if (tid == 0) {
        float s = 0.f;
#pragma unroll
        for (int i = 0; i < 16; i++) s += s_e[i];
        g_psum[blockIdx.x] = s;
        __threadfence();
        unsigned old = atomicAdd(&g_cnt, 1u);
        s_last = (old == (unsigned)(gridDim.x - 1));
    }
    __syncthreads();
    if (s_last) {
        __threadfence();
        float z = (tid < NSB) ? g_psum[tid] : 0.f;
        if (tid + 512 < NSB) z += g_psum[tid + 512];
        s_z[tid] = z;
        __syncthreads();
        for (int st = 256; st > 0; st >>= 1) {
            if (tid < st) s_z[tid] += s_z[tid + st];
            __syncthreads();
        }
        if (tid == 0) {
            g_invZ = 1.f / s_z[0];
            g_cnt = 0;                       // reset for next graph replay
        }
    }
}

// ---------------- kernel 3: probs @ V, split-K=16 (grid (16,16), 512 thr, 4 thr/dim) ----------------
__global__ void __launch_bounds__(512)
k_attnv(const float* __restrict__ cacheV, const int* __restrict__ posp) {
    __shared__ float s_buf[512];
    int pos = *posp;
    int tid = threadIdx.x;
    int d = blockIdx.x * 128 + (tid & 127);     // dim owned
    int qtr = tid >> 7;                         // row quarter 0..3
    int s = blockIdx.y;                         // split 0..15
    float a0 = 0.f, a1 = 0.f, a2 = 0.f, a3 = 0.f;
    int i = s + 16 * qtr;                       // rows: stride 64 per quarter
    for (; i + 192 < pos; i += 256) {
        a0 += g_probs[i]       * __ldcs(&cacheV[(size_t)i * DIM + d]);
        a1 += g_probs[i + 64]  * __ldcs(&cacheV[(size_t)(i + 64) * DIM + d]);
        a2 += g_probs[i + 128] * __ldcs(&cacheV[(size_t)(i + 128) * DIM + d]);
        a3 += g_probs[i + 192] * __ldcs(&cacheV[(size_t)(i + 192) * DIM + d]);
    }
    for (; i < pos; i += 64)
        a0 += g_probs[i] * __ldcs(&cacheV[(size_t)i * DIM + d]);
    if (qtr == 0 && s == (pos & (NSPLIT - 1)))
        a0 += g_probs[pos] * g_qkv[2 * DIM + d];
    s_buf[tid] = (a0 + a1) + (a2 + a3);
    __syncthreads();
    if (tid < 128)
        g_partial[(size_t)s * DIM + blockIdx.x * 128 + tid] =
            (s_buf[tid] + s_buf[tid + 128]) + (s_buf[tid + 256] + s_buf[tid + 384]);
}

// ---------------- kernel 4: o-proj + residual, with inline split-reduce prelude ----------------
// 128 blocks x 512 thr: prelude reduces 16 partials (L2-hot) into s_a with 1/Z,
// then warp-per-row GEMV over 16 rows.
__global__ void __launch_bounds__(512)
k_oproj(const float* __restrict__ ow, const float* __restrict__ ob,
        const float* __restrict__ x) {
    __shared__ float s_a[DIM];
    int tid = threadIdx.x, warp = tid >> 5, lane = tid & 31;

    // prelude: s_a = invZ * sum_s partial[s][:]   (tid owns float4 tid)
    float invZ = g_invZ;
    const float4* p4 = reinterpret_cast<const float4*>(g_partial);
    float4 acc4 = make_float4(0.f, 0.f, 0.f, 0.f);
#pragma unroll
    for (int s = 0; s < NSPLIT; s++) {
        float4 a = p4[(size_t)s * (DIM / 4) + tid];
        acc4.x += a.x; acc4.y += a.y; acc4.z += a.z; acc4.w += a.w;
    }
    reinterpret_cast<float4*>(s_a)[tid] =
        make_float4(acc4.x * invZ, acc4.y * invZ, acc4.z * invZ, acc4.w * invZ);
    __syncthreads();

    int row = blockIdx.x * 16 + warp;
    const float4* w4 = reinterpret_cast<const float4*>(ow + (size_t)row * DIM);
    const float4* sa4 = reinterpret_cast<const float4*>(s_a);
    float acc = 0.f;
#pragma unroll 16
    for (int i = lane; i < DIM / 4; i += 32) {
        float4 a = __ldcs(&w4[i]); float4 b = sa4[i];
        acc += a.x*b.x + a.y*b.y + a.z*b.z + a.w*b.w;
    }
    acc = warp_red(acc);
    if (lane == 0) g_x2[row] = x[row] + acc + ob[row];
}

// ---------------- kernel 5: rmsnorm + fc1 + exact GELU (512 thr, 16 rows/blk, 512 blocks) ----------------
__global__ void __launch_bounds__(512)
k_fc1(const float* __restrict__ mnw,
      const float* __restrict__ w1, const float* __restrict__ b1) {
    __shared__ float s_xn[DIM];
    __shared__ float s_red[16];
    __shared__ float s_inv;
    int tid = threadIdx.x, warp = tid >> 5, lane = tid & 31;

    float4 v0 = reinterpret_cast<const float4*>(g_x2)[tid];
    float ss = v0.x*v0.x + v0.y*v0.y + v0.z*v0.z + v0.w*v0.w;
    ss = warp_red(ss);
    if (lane == 0) s_red[warp] = ss;
    __syncthreads();
    if (tid == 0) {
        float t = 0.f;
#pragma unroll
        for (int i = 0; i < 16; i++) t += s_red[i];
        s_inv = rsqrtf(t * (1.f / DIM) + 1e-6f);
    }
    __syncthreads();
    float inv = s_inv;
    float4 n0 = reinterpret_cast<const float4*>(mnw)[tid];
    float4* sx4 = reinterpret_cast<float4*>(s_xn);
    sx4[tid] = make_float4(v0.x*inv*n0.x, v0.y*inv*n0.y, v0.z*inv*n0.z, v0.w*inv*n0.w);
    __syncthreads();

    int row = blockIdx.x * 16 + warp;       // 0..8191
    const float4* w4 = reinterpret_cast<const float4*>(w1 + (size_t)row * DIM);
    float acc = 0.f;
#pragma unroll 16
    for (int i = lane; i < DIM / 4; i += 32) {
        float4 a = __ldcs(&w4[i]); float4 b = sx4[i];
        acc += a.x*b.x + a.y*b.y + a.z*b.z + a.w*b.w;
    }
    acc = warp_red(acc);
    if (lane == 0) {
        float u = acc + b1[row];
        g_h[row] = 0.5f * u * (1.f + erff(u * 0.70710678118654752f));
    }
}

// ---------------- kernel 6: fc2 + residual -> out (512 thr, 8 rows/blk, 2 warps/row, 256 blocks) ----------------
__global__ void __launch_bounds__(512)
k_fc2(const float* __restrict__ w2, const float* __restrict__ b2,
      float* __restrict__ out) {
    __shared__ float s_h[HID];
    __shared__ float s_part[8][2];
    int tid = threadIdx.x, warp = tid >> 5, lane = tid & 31;
    float4* sh4 = reinterpret_cast<float4*>(s_h);
    const float4* h4 = reinterpret_cast<const float4*>(g_h);
#pragma unroll
    for (int i = 0; i < 4; i++) sh4[tid + 512 * i] = h4[tid + 512 * i];
    __syncthreads();

    int rl = warp >> 1, half = warp & 1;
    int row = blockIdx.x * 8 + rl;
    const float4* w4 = reinterpret_cast<const float4*>(w2 + (size_t)row * HID);
    float acc = 0.f;
    int base = half * 1024;
#pragma unroll 16
    for (int i = base + lane; i < base + 1024; i += 32) {
        float4 a = __ldcs(&w4[i]); float4 b = sh4[i];
        acc += a.x*b.x + a.y*b.y + a.z*b.z + a.w*b.w;
    }
    acc = warp_red(acc);
    if (lane == 0) s_part[rl][half] = acc;
    __syncthreads();
    if (tid < 8) {
        int r = blockIdx.x * 8 + tid;
        out[r] = g_x2[r] + s_part[tid][0] + s_part[tid][1] + b2[r];
    }
}

// ---------------- launch ----------------
extern "C" void kernel_launch(void* const* d_in, const int* in_sizes, int n_in,
                              void* d_out, int out_size) {
    const float* x      = (const float*)d_in[0];
    const float* cacheK = (const float*)d_in[1];
    const float* cacheV = (const float*)d_in[2];
    const float* anw    = (const float*)d_in[3];
    const float* qw     = (const float*)d_in[4];
    const float* qb     = (const float*)d_in[5];
    const float* kw     = (const float*)d_in[6];
    const float* kb     = (const float*)d_in[7];
    const float* vw     = (const float*)d_in[8];
    const float* vb     = (const float*)d_in[9];
    const float* ow     = (const float*)d_in[10];
    const float* ob     = (const float*)d_in[11];
    const float* mnw    = (const float*)d_in[12];
    const float* w1     = (const float*)d_in[13];
    const float* b1     = (const float*)d_in[14];
    const float* w2     = (const float*)d_in[15];
    const float* b2     = (const float*)d_in[16];
    const int*   posp   = (const int*)d_in[17];
    float* out = (float*)d_out;

    k_qkv<<<(3 * DIM) / 16, 512>>>(x, anw, qw, qb, kw, kb, vw, vb);
    k_scores<<<NSB, 512>>>(cacheK, posp);
    k_attnv<<<dim3(DIM / 128, NSPLIT), 512>>>(cacheV, posp);
    k_oproj<<<DIM / 16, 512>>>(ow, ob, x);
    k_fc1<<<HID / 16, 512>>>(mnw, w1, b1);
    k_fc2<<<DIM / 8, 512>>>(w2, b2, out);
}

// round 14
// speedup vs baseline: 1.0245x; 1.0245x over previous
#include <cuda_runtime.h>
#include <math.h>

#define DIM 2048
#define HID 8192
#define MAX_LEN 8192
#define NSPLIT 16
#define NSB ((MAX_LEN + 16) / 16)  // 513 score blocks (16 rows each)

// ---------------- scratch ----------------
__device__ float g_qkv[3 * DIM];            // q | k | v
__device__ float g_probs[MAX_LEN + 1];      // unnormalized exp(score)
__device__ float g_psum[NSB];               // per-block partial sums of exp
__device__ float g_invZ;                    // 1/sum(exp)
__device__ unsigned g_cnt;                  // last-block counter (self-resetting)
__device__ float g_partial[NSPLIT * DIM];   // split-K attention partials
__device__ float g_x2[DIM];                 // x + attn@oW + ob
__device__ float g_h[HID];                  // gelu(fc1)

__device__ __forceinline__ float warp_red(float v) {
#pragma unroll
    for (int o = 16; o > 0; o >>= 1) v += __shfl_xor_sync(0xffffffffu, v, o);
    return v;
}

// bulk L2 prefetch: one instruction puts `bytes` of gmem in flight toward L2
__device__ __forceinline__ void l2_prefetch(const void* p, unsigned bytes) {
    asm volatile("cp.async.bulk.prefetch.L2.global [%0], %1;"
                 :: "l"(p), "r"(bytes) : "memory");
}

// ---------------- kernel 1: fused rmsnorm + QKV GEMV (512 thr, 16 rows/blk, 384 blocks) ----------------
__global__ void __launch_bounds__(512)
k_qkv(const float* __restrict__ x, const float* __restrict__ anw,
      const float* __restrict__ qw, const float* __restrict__ qb,
      const float* __restrict__ kw, const float* __restrict__ kb,
      const float* __restrict__ vw, const float* __restrict__ vb) {
    __shared__ float s_xn[DIM];
    __shared__ float s_red[16];
    __shared__ float s_inv;
    int tid = threadIdx.x, warp = tid >> 5, lane = tid & 31;

    int r = blockIdx.x * 16 + warp;         // 0..6143
    int m = r >> 11, j = r & (DIM - 1);
    const float* W = (m == 0) ? qw : (m == 1) ? kw : vw;
    const float* B = (m == 0) ? qb : (m == 1) ? kb : vb;
    const float4* w4 = reinterpret_cast<const float4*>(W + (size_t)j * DIM);
    if (lane == 0) l2_prefetch(w4, DIM * 4);          // whole row in flight early

    float4 v0 = reinterpret_cast<const float4*>(x)[tid];
    float ss = v0.x*v0.x + v0.y*v0.y + v0.z*v0.z + v0.w*v0.w;
    ss = warp_red(ss);
    if (lane == 0) s_red[warp] = ss;
    __syncthreads();
    if (tid == 0) {
        float t = 0.f;
#pragma unroll
        for (int i = 0; i < 16; i++) t += s_red[i];
        s_inv = rsqrtf(t * (1.f / DIM) + 1e-6f);
    }
    __syncthreads();
    float inv = s_inv;
    float4 n0 = reinterpret_cast<const float4*>(anw)[tid];
    float4* sx4 = reinterpret_cast<float4*>(s_xn);
    sx4[tid] = make_float4(v0.x*inv*n0.x, v0.y*inv*n0.y, v0.z*inv*n0.z, v0.w*inv*n0.w);
    __syncthreads();

    float acc = 0.f;
#pragma unroll 16
    for (int i = lane; i < DIM / 4; i += 32) {
        float4 a = __ldcs(&w4[i]); float4 b = sx4[i];
        acc += a.x*b.x + a.y*b.y + a.z*b.z + a.w*b.w;
    }
    acc = warp_red(acc);
    if (lane == 0) g_qkv[r] = acc + B[j];
}

// ---------------- kernel 2: scores -> exp, last block computes 1/Z (512 thr, 16 rows/blk) ----------------
__global__ void __launch_bounds__(512)
k_scores(const float* __restrict__ cacheK, const int* __restrict__ posp) {
    __shared__ float s_q[DIM];
    __shared__ float s_e[16];
    __shared__ float s_z[512];
    __shared__ bool s_last;
    int pos = *posp;
    int tid = threadIdx.x, warp = tid >> 5, lane = tid & 31;

    int row = blockIdx.x * 16 + warp;
    const float* krow = (row == pos) ? (g_qkv + DIM) : (cacheK + (size_t)row * DIM);
    if (lane == 0 && row <= pos) l2_prefetch(krow, DIM * 4);

    float4* sq4 = reinterpret_cast<float4*>(s_q);
    sq4[tid] = reinterpret_cast<const float4*>(g_qkv)[tid];
    if (tid < 16) s_e[tid] = 0.f;
    __syncthreads();

    if (row <= pos) {
        const float4* k4 = reinterpret_cast<const float4*>(krow);
        float acc = 0.f;
#pragma unroll 16
        for (int i = lane; i < DIM / 4; i += 32) {
            float4 a = __ldcs(&k4[i]); float4 b = sq4[i];
            acc += a.x*b.x + a.y*b.y + a.z*b.z + a.w*b.w;
        }
        acc = warp_red(acc);
        if (lane == 0) {
            float e = __expf(acc * 0.022097086912079608f);  // 1/sqrt(2048)
            g_probs[row] = e;
            s_e[warp] = e;
        }
    }
    __syncthreads();
    if (tid == 0) {
        float s = 0.f;
#pragma unroll
        for (int i = 0; i < 16; i++) s += s_e[i];
        g_psum[blockIdx.x] = s;
        __threadfence();
        unsigned old = atomicAdd(&g_cnt, 1u);
        s_last = (old == (unsigned)(gridDim.x - 1));
    }
    __syncthreads();
    if (s_last) {
        __threadfence();
        float z = (tid < NSB) ? g_psum[tid] : 0.f;
        if (tid + 512 < NSB) z += g_psum[tid + 512];
        s_z[tid] = z;
        __syncthreads();
        for (int st = 256; st > 0; st >>= 1) {
            if (tid < st) s_z[tid] += s_z[tid + st];
            __syncthreads();
        }
        if (tid == 0) {
            g_invZ = 1.f / s_z[0];
            g_cnt = 0;                       // reset for next graph replay
        }
    }
}

// ---------------- kernel 3: probs @ V, split-K=16 (grid (16,16), 512 thr, 4 thr/dim) ----------------
__global__ void __launch_bounds__(512)
k_attnv(const float* __restrict__ cacheV, const int* __restrict__ posp) {
    __shared__ float s_buf[512];
    int pos = *posp;
    int tid = threadIdx.x;
    int d = blockIdx.x * 128 + (tid & 127);     // dim owned
    int qtr = tid >> 7;                         // row quarter 0..3
    int s = blockIdx.y;                         // split 0..15
    float a0 = 0.f, a1 = 0.f, a2 = 0.f, a3 = 0.f;
    int i = s + 16 * qtr;                       // rows: stride 64 per quarter
    for (; i + 192 < pos; i += 256) {
        a0 += g_probs[i]       * __ldcs(&cacheV[(size_t)i * DIM + d]);
        a1 += g_probs[i + 64]  * __ldcs(&cacheV[(size_t)(i + 64) * DIM + d]);
        a2 += g_probs[i + 128] * __ldcs(&cacheV[(size_t)(i + 128) * DIM + d]);
        a3 += g_probs[i + 192] * __ldcs(&cacheV[(size_t)(i + 192) * DIM + d]);
    }
    for (; i < pos; i += 64)
        a0 += g_probs[i] * __ldcs(&cacheV[(size_t)i * DIM + d]);
    if (qtr == 0 && s == (pos & (NSPLIT - 1)))
        a0 += g_probs[pos] * g_qkv[2 * DIM + d];
    s_buf[tid] = (a0 + a1) + (a2 + a3);
    __syncthreads();
    if (tid < 128)
        g_partial[(size_t)s * DIM + blockIdx.x * 128 + tid] =
            (s_buf[tid] + s_buf[tid + 128]) + (s_buf[tid + 256] + s_buf[tid + 384]);
}

// ---------------- kernel 4: o-proj + residual, with inline split-reduce prelude ----------------
__global__ void __launch_bounds__(512)
k_oproj(const float* __restrict__ ow, const float* __restrict__ ob,
        const float* __restrict__ x) {
    __shared__ float s_a[DIM];
    int tid = threadIdx.x, warp = tid >> 5, lane = tid & 31;

    int row = blockIdx.x * 16 + warp;
    const float4* w4 = reinterpret_cast<const float4*>(ow + (size_t)row * DIM);
    if (lane == 0) l2_prefetch(w4, DIM * 4);

    // prelude: s_a = invZ * sum_s partial[s][:]   (tid owns float4 tid)
    float invZ = g_invZ;
    const float4* p4 = reinterpret_cast<const float4*>(g_partial);
    float4 acc4 = make_float4(0.f, 0.f, 0.f, 0.f);
#pragma unroll
    for (int s = 0; s < NSPLIT; s++) {
        float4 a = p4[(size_t)s * (DIM / 4) + tid];
        acc4.x += a.x; acc4.y += a.y; acc4.z += a.z; acc4.w += a.w;
    }
    reinterpret_cast<float4*>(s_a)[tid] =
        make_float4(acc4.x * invZ, acc4.y * invZ, acc4.z * invZ, acc4.w * invZ);
    __syncthreads();

    const float4* sa4 = reinterpret_cast<const float4*>(s_a);
    float acc = 0.f;
#pragma unroll 16
    for (int i = lane; i < DIM / 4; i += 32) {
        float4 a = __ldcs(&w4[i]); float4 b = sa4[i];
        acc += a.x*b.x + a.y*b.y + a.z*b.z + a.w*b.w;
    }
    acc = warp_red(acc);
    if (lane == 0) g_x2[row] = x[row] + acc + ob[row];
}

// ---------------- kernel 5: rmsnorm + fc1 + exact GELU (512 thr, 16 rows/blk, 512 blocks) ----------------
__global__ void __launch_bounds__(512)
k_fc1(const float* __restrict__ mnw,
      const float* __restrict__ w1, const float* __restrict__ b1) {
    __shared__ float s_xn[DIM];
    __shared__ float s_red[16];
    __shared__ float s_inv;
    int tid = threadIdx.x, warp = tid >> 5, lane = tid & 31;

    int row = blockIdx.x * 16 + warp;       // 0..8191
    const float4* w4 = reinterpret_cast<const float4*>(w1 + (size_t)row * DIM);
    if (lane == 0) l2_prefetch(w4, DIM * 4);

    float4 v0 = reinterpret_cast<const float4*>(g_x2)[tid];
    float ss = v0.x*v0.x + v0.y*v0.y + v0.z*v0.z + v0.w*v0.w;
    ss = warp_red(ss);
    if (lane == 0) s_red[warp] = ss;
    __syncthreads();
    if (tid == 0) {
        float t = 0.f;
#pragma unroll
        for (int i = 0; i < 16; i++) t += s_red[i];
        s_inv = rsqrtf(t * (1.f / DIM) + 1e-6f);
    }
    __syncthreads();
    float inv = s_inv;
    float4 n0 = reinterpret_cast<const float4*>(mnw)[tid];
    float4* sx4 = reinterpret_cast<float4*>(s_xn);
    sx4[tid] = make_float4(v0.x*inv*n0.x, v0.y*inv*n0.y, v0.z*inv*n0.z, v0.w*inv*n0.w);
    __syncthreads();

    float acc = 0.f;
#pragma unroll 16
    for (int i = lane; i < DIM / 4; i += 32) {
        float4 a = __ldcs(&w4[i]); float4 b = sx4[i];
        acc += a.x*b.x + a.y*b.y + a.z*b.z + a.w*b.w;
    }
    acc = warp_red(acc);
    if (lane == 0) {
        float u = acc + b1[row];
        g_h[row] = 0.5f * u * (1.f + erff(u * 0.70710678118654752f));
    }
}

// ---------------- kernel 6: fc2 + residual -> out (512 thr, 8 rows/blk, 2 warps/row, 256 blocks) ----------------
__global__ void __launch_bounds__(512)
k_fc2(const float* __restrict__ w2, const float* __restrict__ b2,
      float* __restrict__ out) {
    __shared__ float s_h[HID];
    __shared__ float s_part[8][2];
    int tid = threadIdx.x, warp = tid >> 5, lane = tid & 31;

    int rl = warp >> 1, half = warp & 1;
    int row = blockIdx.x * 8 + rl;
    const float4* w4 = reinterpret_cast<const float4*>(w2 + (size_t)row * HID);
    int base = half * 1024;
    if (lane == 0) l2_prefetch(w4 + base, 1024 * 16);   // this warp's 16KB half-row

    float4* sh4 = reinterpret_cast<float4*>(s_h);
    const float4* h4 = reinterpret_cast<const float4*>(g_h);
#pragma unroll
    for (int i = 0; i < 4; i++) sh4[tid + 512 * i] = h4[tid + 512 * i];
    __syncthreads();

    float acc = 0.f;
#pragma unroll 16
    for (int i = base + lane; i < base + 1024; i += 32) {
        float4 a = __ldcs(&w4[i]); float4 b = sh4[i];
        acc += a.x*b.x + a.y*b.y + a.z*b.z + a.w*b.w;
    }
    acc = warp_red(acc);
    if (lane == 0) s_part[rl][half] = acc;
    __syncthreads();
    if (tid < 8) {
        int r = blockIdx.x * 8 + tid;
        out[r] = g_x2[r] + s_part[tid][0] + s_part[tid][1] + b2[r];
    }
}

// ---------------- launch ----------------
extern "C" void kernel_launch(void* const* d_in, const int* in_sizes, int n_in,
                              void* d_out, int out_size) {
    const float* x      = (const float*)d_in[0];
    const float* cacheK = (const float*)d_in[1];
    const float* cacheV = (const float*)d_in[2];
    const float* anw    = (const float*)d_in[3];
    const float* qw     = (const float*)d_in[4];
    const float* qb     = (const float*)d_in[5];
    const float* kw     = (const float*)d_in[6];
    const float* kb     = (const float*)d_in[7];
    const float* vw     = (const float*)d_in[8];
    const float* vb     = (const float*)d_in[9];
    const float* ow     = (const float*)d_in[10];
    const float* ob     = (const float*)d_in[11];
    const float* mnw    = (const float*)d_in[12];
    const float* w1     = (const float*)d_in[13];
    const float* b1     = (const float*)d_in[14];
    const float* w2     = (const float*)d_in[15];
    const float* b2     = (const float*)d_in[16];
    const int*   posp   = (const int*)d_in[17];
    float* out = (float*)d_out;

    k_qkv<<<(3 * DIM) / 16, 512>>>(x, anw, qw, qb, kw, kb, vw, vb);
    k_scores<<<NSB, 512>>>(cacheK, posp);
    k_attnv<<<dim3(DIM / 128, NSPLIT), 512>>>(cacheV, posp);
    k_oproj<<<DIM / 16, 512>>>(ow, ob, x);
    k_fc1<<<HID / 16, 512>>>(mnw, w1, b1);
    k_fc2<<<DIM / 8, 512>>>(w2, b2, out);
}

// round 16
// speedup vs baseline: 1.0309x; 1.0063x over previous
#include <cuda_runtime.h>
#include <math.h>

#define DIM 2048
#define HID 8192
#define MAX_LEN 8192
#define NSPLIT 16
#define NSB ((MAX_LEN + 16) / 16)  // 513 score blocks (16 rows each)

// ---------------- scratch ----------------
__device__ float g_qkv[3 * DIM];            // q | k | v
__device__ float g_probs[MAX_LEN + 1];      // unnormalized exp(score)
__device__ float g_psum[NSB];               // per-block partial sums of exp
__device__ float g_invZ;                    // 1/sum(exp)
__device__ unsigned g_cnt;                  // last-block counter (self-resetting)
__device__ float g_partial[NSPLIT * DIM];   // split-K attention partials
__device__ float g_x2[DIM];                 // x + attn@oW + ob
__device__ float g_h[HID];                  // gelu(fc1)

__device__ __forceinline__ float warp_red(float v) {
#pragma unroll
    for (int o = 16; o > 0; o >>= 1) v += __shfl_xor_sync(0xffffffffu, v, o);
    return v;
}

__device__ __forceinline__ void l2_prefetch(const void* p, unsigned bytes) {
    asm volatile("cp.async.bulk.prefetch.L2.global [%0], %1;"
                 :: "l"(p), "r"(bytes) : "memory");
}

// warp dot over `n4` float4s (n4 multiple of 256): 8-deep explicit load batches
__device__ __forceinline__ float warp_dot_batched(const float4* __restrict__ w4,
                                                  const float4* __restrict__ s4,
                                                  int lane, int n4) {
    float acc = 0.f;
    for (int base = 0; base < n4; base += 256) {
        float4 A0 = __ldcs(&w4[base + lane]);
        float4 A1 = __ldcs(&w4[base + lane + 32]);
        float4 A2 = __ldcs(&w4[base + lane + 64]);
        float4 A3 = __ldcs(&w4[base + lane + 96]);
        float4 A4 = __ldcs(&w4[base + lane + 128]);
        float4 A5 = __ldcs(&w4[base + lane + 160]);
        float4 A6 = __ldcs(&w4[base + lane + 192]);
        float4 A7 = __ldcs(&w4[base + lane + 224]);
        float4 b;
        b = s4[base + lane];       acc += A0.x*b.x + A0.y*b.y + A0.z*b.z + A0.w*b.w;
        b = s4[base + lane + 32];  acc += A1.x*b.x + A1.y*b.y + A1.z*b.z + A1.w*b.w;
        b = s4[base + lane + 64];  acc += A2.x*b.x + A2.y*b.y + A2.z*b.z + A2.w*b.w;
        b = s4[base + lane + 96];  acc += A3.x*b.x + A3.y*b.y + A3.z*b.z + A3.w*b.w;
        b = s4[base + lane + 128]; acc += A4.x*b.x + A4.y*b.y + A4.z*b.z + A4.w*b.w;
        b = s4[base + lane + 160]; acc += A5.x*b.x + A5.y*b.y + A5.z*b.z + A5.w*b.w;
        b = s4[base + lane + 192]; acc += A6.x*b.x + A6.y*b.y + A6.z*b.z + A6.w*b.w;
        b = s4[base + lane + 224]; acc += A7.x*b.x + A7.y*b.y + A7.z*b.z + A7.w*b.w;
    }
    return acc;
}

// ---------------- kernel 1: fused rmsnorm + QKV GEMV (512 thr, 16 rows/blk, 384 blocks) ----------------
__global__ void __launch_bounds__(512)
k_qkv(const float* __restrict__ x, const float* __restrict__ anw,
      const float* __restrict__ qw, const float* __restrict__ qb,
      const float* __restrict__ kw, const float* __restrict__ kb,
      const float* __restrict__ vw, const float* __restrict__ vb) {
    __shared__ float s_xn[DIM];
    __shared__ float s_red[16];
    __shared__ float s_inv;
    int tid = threadIdx.x, warp = tid >> 5, lane = tid & 31;

    int r = blockIdx.x * 16 + warp;         // 0..6143
    int m = r >> 11, j = r & (DIM - 1);
    const float* W = (m == 0) ? qw : (m == 1) ? kw : vw;
    const float* B = (m == 0) ? qb : (m == 1) ? kb : vb;
    const float4* w4 = reinterpret_cast<const float4*>(W + (size_t)j * DIM);
    if (lane == 0) l2_prefetch(w4, DIM * 4);

    float4 v0 = reinterpret_cast<const float4*>(x)[tid];
    float ss = v0.x*v0.x + v0.y*v0.y + v0.z*v0.z + v0.w*v0.w;
    ss = warp_red(ss);
    if (lane == 0) s_red[warp] = ss;
    __syncthreads();
    if (tid == 0) {
        float t = 0.f;
#pragma unroll
        for (int i = 0; i < 16; i++) t += s_red[i];
        s_inv = rsqrtf(t * (1.f / DIM) + 1e-6f);
    }
    __syncthreads();
    float inv = s_inv;
    float4 n0 = reinterpret_cast<const float4*>(anw)[tid];
    float4* sx4 = reinterpret_cast<float4*>(s_xn);
    sx4[tid] = make_float4(v0.x*inv*n0.x, v0.y*inv*n0.y, v0.z*inv*n0.z, v0.w*inv*n0.w);
    __syncthreads();

    float acc = warp_dot_batched(w4, sx4, lane, DIM / 4);
    acc = warp_red(acc);
    if (lane == 0) g_qkv[r] = acc + B[j];
}

// ---------------- kernel 2: scores -> exp, last block computes 1/Z (512 thr, 16 rows/blk) ----------------
__global__ void __launch_bounds__(512)
k_scores(const float* __restrict__ cacheK, const int* __restrict__ posp) {
    __shared__ float s_q[DIM];
    __shared__ float s_e[16];
    __shared__ float s_z[512];
    __shared__ bool s_last;
    int pos = *posp;
    int tid = threadIdx.x, warp = tid >> 5, lane = tid & 31;

    int row = blockIdx.x * 16 + warp;
    const float* krow = (row == pos) ? (g_qkv + DIM) : (cacheK + (size_t)row * DIM);
    if (lane == 0 && row <= pos) l2_prefetch(krow, DIM * 4);

    float4* sq4 = reinterpret_cast<float4*>(s_q);
    sq4[tid] = reinterpret_cast<const float4*>(g_qkv)[tid];
    if (tid < 16) s_e[tid] = 0.f;
    __syncthreads();

    if (row <= pos) {
        const float4* k4 = reinterpret_cast<const float4*>(krow);
        float acc = warp_dot_batched(k4, sq4, lane, DIM / 4);
        acc = warp_red(acc);
        if (lane == 0) {
            float e = __expf(acc * 0.022097086912079608f);  // 1/sqrt(2048)
            g_probs[row] = e;
            s_e[warp] = e;
        }
    }
    __syncthreads();
    if (tid == 0) {
        float s = 0.f;
#pragma unroll
        for (int i = 0; i < 16; i++) s += s_e[i];
        g_psum[blockIdx.x] = s;
        __threadfence();
        unsigned old = atomicAdd(&g_cnt, 1u);
        s_last = (old == (unsigned)(gridDim.x - 1));
    }
    __syncthreads();
    if (s_last) {
        __threadfence();
        float z = (tid < NSB) ? g_psum[tid] : 0.f;
        if (tid + 512 < NSB) z += g_psum[tid + 512];
        s_z[tid] = z;
        __syncthreads();
        for (int st = 256; st > 0; st >>= 1) {
            if (tid < st) s_z[tid] += s_z[tid + st];
            __syncthreads();
        }
        if (tid == 0) {
            g_invZ = 1.f / s_z[0];
            g_cnt = 0;                       // reset for next graph replay
        }
    }
}

// ---------------- kernel 3: probs @ V, split-K=16 (grid (16,16), 512 thr, 4 thr/dim) ----------------
__global__ void __launch_bounds__(512)
k_attnv(const float* __restrict__ cacheV, const int* __restrict__ posp) {
    __shared__ float s_buf[512];
    int pos = *posp;
    int tid = threadIdx.x;
    int d = blockIdx.x * 128 + (tid & 127);     // dim owned
    int qtr = tid >> 7;                         // row quarter 0..3
    int s = blockIdx.y;                         // split 0..15
    float a0 = 0.f, a1 = 0.f, a2 = 0.f, a3 = 0.f;
    int i = s + 16 * qtr;                       // rows: stride 64 per quarter
    for (; i + 192 < pos; i += 256) {
        a0 += g_probs[i]       * __ldcs(&cacheV[(size_t)i * DIM + d]);
        a1 += g_probs[i + 64]  * __ldcs(&cacheV[(size_t)(i + 64) * DIM + d]);
        a2 += g_probs[i + 128] * __ldcs(&cacheV[(size_t)(i + 128) * DIM + d]);
        a3 += g_probs[i + 192] * __ldcs(&cacheV[(size_t)(i + 192) * DIM + d]);
    }
    for (; i < pos; i += 64)
        a0 += g_probs[i] * __ldcs(&cacheV[(size_t)i * DIM + d]);
    if (qtr == 0 && s == (pos & (NSPLIT - 1)))
        a0 += g_probs[pos] * g_qkv[2 * DIM + d];
    s_buf[tid] = (a0 + a1) + (a2 + a3);
    __syncthreads();
    if (tid < 128)
        g_partial[(size_t)s * DIM + blockIdx.x * 128 + tid] =
            (s_buf[tid] + s_buf[tid + 128]) + (s_buf[tid + 256] + s_buf[tid + 384]);
}

// ---------------- kernel 4: o-proj + residual (8 rows/blk, 2 warps/row, 256 blocks) ----------------
__global__ void __launch_bounds__(512)
k_oproj(const float* __restrict__ ow, const float* __restrict__ ob,
        const float* __restrict__ x) {
    __shared__ float s_a[DIM];
    __shared__ float s_part[8][2];
    int tid = threadIdx.x, warp = tid >> 5, lane = tid & 31;

    int rl = warp >> 1, half = warp & 1;
    int row = blockIdx.x * 8 + rl;
    const float4* w4 = reinterpret_cast<const float4*>(ow + (size_t)row * DIM)
                       + half * 256;
    if (lane == 0) l2_prefetch(w4, 256 * 16);

    // prelude: s_a = invZ * sum_s partial[s][:]   (tid owns float4 tid)
    float invZ = g_invZ;
    const float4* p4 = reinterpret_cast<const float4*>(g_partial);
    float4 acc4 = make_float4(0.f, 0.f, 0.f, 0.f);
#pragma unroll
    for (int s = 0; s < NSPLIT; s++) {
        float4 a = p4[(size_t)s * (DIM / 4) + tid];
        acc4.x += a.x; acc4.y += a.y; acc4.z += a.z; acc4.w += a.w;
    }
    reinterpret_cast<float4*>(s_a)[tid] =
        make_float4(acc4.x * invZ, acc4.y * invZ, acc4.z * invZ, acc4.w * invZ);
    __syncthreads();

    const float4* sa4 = reinterpret_cast<const float4*>(s_a) + half * 256;
    float acc = warp_dot_batched(w4, sa4, lane, 256);
    acc = warp_red(acc);
    if (lane == 0) s_part[rl][half] = acc;
    __syncthreads();
    if (tid < 8) {
        int r = blockIdx.x * 8 + tid;
        g_x2[r] = x[r] + s_part[tid][0] + s_part[tid][1] + ob[r];
    }
}

// ---------------- kernel 5: rmsnorm + fc1 + exact GELU (512 thr, 16 rows/blk, 512 blocks) ----------------
__global__ void __launch_bounds__(512)
k_fc1(const float* __restrict__ mnw,
      const float* __restrict__ w1, const float* __restrict__ b1) {
    __shared__ float s_xn[DIM];
    __shared__ float s_red[16];
    __shared__ float s_inv;
    int tid = threadIdx.x, warp = tid >> 5, lane = tid & 31;

    int row = blockIdx.x * 16 + warp;       // 0..8191
    const float4* w4 = reinterpret_cast<const float4*>(w1 + (size_t)row * DIM);
    if (lane == 0) l2_prefetch(w4, DIM * 4);

    float4 v0 = reinterpret_cast<const float4*>(g_x2)[tid];
    float ss = v0.x*v0.x + v0.y*v0.y + v0.z*v0.z + v0.w*v0.w;
    ss = warp_red(ss);
    if (lane == 0) s_red[warp] = ss;
    __syncthreads();
    if (tid == 0) {
        float t = 0.f;
#pragma unroll
        for (int i = 0; i < 16; i++) t += s_red[i];
        s_inv = rsqrtf(t * (1.f / DIM) + 1e-6f);
    }
    __syncthreads();
    float inv = s_inv;
    float4 n0 = reinterpret_cast<const float4*>(mnw)[tid];
    float4* sx4 = reinterpret_cast<float4*>(s_xn);
    sx4[tid] = make_float4(v0.x*inv*n0.x, v0.y*inv*n0.y, v0.z*inv*n0.z, v0.w*inv*n0.w);
    __syncthreads();

    float acc = warp_dot_batched(w4, sx4, lane, DIM / 4);
    acc = warp_red(acc);
    if (lane == 0) {
        float u = acc + b1[row];
        g_h[row] = 0.5f * u * (1.f + erff(u * 0.70710678118654752f));
    }
}

// ---------------- kernel 6: fc2 + residual -> out (512 thr, 8 rows/blk, 2 warps/row, 256 blocks) ----------------
__global__ void __launch_bounds__(512)
k_fc2(const float* __restrict__ w2, const float* __restrict__ b2,
      float* __restrict__ out) {
    __shared__ float s_h[HID];
    __shared__ float s_part[8][2];
    int tid = threadIdx.x, warp = tid >> 5, lane = tid & 31;

    int rl = warp >> 1, half = warp & 1;
    int row = blockIdx.x * 8 + rl;
    const float4* w4 = reinterpret_cast<const float4*>(w2 + (size_t)row * HID)
                       + half * 1024;
    if (lane == 0) l2_prefetch(w4, 1024 * 16);

    float4* sh4 = reinterpret_cast<float4*>(s_h);
    const float4* h4 = reinterpret_cast<const float4*>(g_h);
#pragma unroll
    for (int i = 0; i < 4; i++) sh4[tid + 512 * i] = h4[tid + 512 * i];
    __syncthreads();

    const float4* sh = reinterpret_cast<const float4*>(s_h) + half * 1024;
    float acc = warp_dot_batched(w4, sh, lane, 1024);
    acc = warp_red(acc);
    if (lane == 0) s_part[rl][half] = acc;
    __syncthreads();
    if (tid < 8) {
        int r = blockIdx.x * 8 + tid;
        out[r] = g_x2[r] + s_part[tid][0] + s_part[tid][1] + b2[r];
    }
}

// ---------------- launch ----------------
extern "C" void kernel_launch(void* const* d_in, const int* in_sizes, int n_in,
                              void* d_out, int out_size) {
    const float* x      = (const float*)d_in[0];
    const float* cacheK = (const float*)d_in[1];
    const float* cacheV = (const float*)d_in[2];
    const float* anw    = (const float*)d_in[3];
    const float* qw     = (const float*)d_in[4];
    const float* qb     = (const float*)d_in[5];
    const float* kw     = (const float*)d_in[6];
    const float* kb     = (const float*)d_in[7];
    const float* vw     = (const float*)d_in[8];
    const float* vb     = (const float*)d_in[9];
    const float* ow     = (const float*)d_in[10];
    const float* ob     = (const float*)d_in[11];
    const float* mnw    = (const float*)d_in[12];
    const float* w1     = (const float*)d_in[13];
    const float* b1     = (const float*)d_in[14];
    const float* w2     = (const float*)d_in[15];
    const float* b2     = (const float*)d_in[16];
    const int*   posp   = (const int*)d_in[17];
    float* out = (float*)d_out;

    k_qkv<<<(3 * DIM) / 16, 512>>>(x, anw, qw, qb, kw, kb, vw, vb);
    k_scores<<<NSB, 512>>>(cacheK, posp);
    k_attnv<<<dim3(DIM / 128, NSPLIT), 512>>>(cacheV, posp);
    k_oproj<<<DIM / 8, 512>>>(ow, ob, x);
    k_fc1<<<HID / 16, 512>>>(mnw, w1, b1);
    k_fc2<<<DIM / 8, 512>>>(w2, b2, out);
}